// round 6
// baseline (speedup 1.0000x reference)
#include <cuda_runtime.h>
#include <math.h>
#include <stdint.h>

#define BB 4
#define SQ 2048
#define SK 2048
#define DD 512
#define HH 8
#define HDIM 64
#define FSCALE 0.125f
#define LNEPS 1e-5f

#define OUT_ELEMS ((size_t)BB * SQ * DD)
#define ATTN_ELEMS ((size_t)BB * HH * SQ * (size_t)SK)

// ---- scratch ----
__device__ float g_qlin[BB * SQ * DD];
__device__ float g_klin[BB * SK * DD];
__device__ float g_vlin[BB * SK * DD];
__device__ float g_ctx [BB * SQ * DD];
__device__ float g_rowsum[(size_t)BB * HH * SQ];
__device__ float g_attn_scratch[ATTN_ELEMS];

// ---- tf32 helpers ----
__device__ __forceinline__ uint32_t f2tf(float f) {
    uint32_t u;
    asm("cvt.rna.tf32.f32 %0, %1;" : "=r"(u) : "f"(f));
    return u;
}
__device__ __forceinline__ float f2tff(float f) {
    return __uint_as_float(f2tf(f));
}

__device__ __forceinline__ void mma_tf32(float* c, const uint32_t* a, const uint32_t* b) {
    asm volatile(
        "mma.sync.aligned.m16n8k8.row.col.f32.tf32.tf32.f32 "
        "{%0,%1,%2,%3}, {%4,%5,%6,%7}, {%8,%9}, {%0,%1,%2,%3};"
        : "+f"(c[0]), "+f"(c[1]), "+f"(c[2]), "+f"(c[3])
        : "r"(a[0]), "r"(a[1]), "r"(a[2]), "r"(a[3]), "r"(b[0]), "r"(b[1]));
}

// Fragment-major block strides (floats). Padding avoids STS bank conflicts.
#define ABLK 132   // A-frag block: 32 lanes * 4 regs = 128 + 4 pad
#define BBLK 68    // B-frag block: 32 lanes * 2 regs = 64 + 4 pad
#define SP   68    // row-major staging stride (<=64 data cols)
#define SPL  132   // linear epilogue staging stride (128 data cols + 4 pad)

// Store float4 of A-operand (row r, cols c..c+3, c%4==0) in fragment-major form.
__device__ __forceinline__ void stA4(float* buf, int r, int c, float4 v) {
    int blk   = ((r >> 4) << 3) + (c >> 3);
    int lane0 = (r & 7) * 4;
    int reg   = ((r >> 3) & 1) + (((c >> 2) & 1) << 1);
    float* p = buf + blk * ABLK + lane0 * 4 + reg;
    p[0] = v.x; p[4] = v.y; p[8] = v.z; p[12] = v.w;
}
// Store float4 of B-operand (n-row n, cols k..k+3) fragment-major.
__device__ __forceinline__ void stB4(float* buf, int n, int k, float4 v) {
    int blk   = ((n >> 3) << 3) + (k >> 3);
    int lane0 = (n & 7) * 4;
    int reg   = (k >> 2) & 1;
    float* p = buf + blk * BBLK + lane0 * 2 + reg;
    p[0] = v.x; p[2] = v.y; p[4] = v.z; p[6] = v.w;
}
// Store float4 of V (row kv, cols d..d+3) as B-operand (n=d, k=kv) fragment-major.
__device__ __forceinline__ void stV4(float* buf, int kv, int d, float4 v) {
    int blk  = ((d >> 3) << 3) + (kv >> 3);
    int lane = ((d & 7) << 2) + (kv & 3);
    int reg  = (kv >> 2) & 1;
    float* p = buf + blk * BBLK + lane * 2 + reg;
    p[0] = v.x; p[8] = v.y; p[16] = v.z; p[24] = v.w;
}

__device__ __forceinline__ void ldAfrag(uint32_t* a, const float* buf, int m16, int kc8, int lane) {
    float4 v = *(const float4*)(buf + (m16 * 8 + kc8) * ABLK + lane * 4);
    a[0] = __float_as_uint(v.x); a[1] = __float_as_uint(v.y);
    a[2] = __float_as_uint(v.z); a[3] = __float_as_uint(v.w);
}
__device__ __forceinline__ void ldBfrag(uint32_t* b, const float* buf, int n8, int kc8, int lane) {
    float2 v = *(const float2*)(buf + (n8 * 8 + kc8) * BBLK + lane * 2);
    b[0] = __float_as_uint(v.x); b[1] = __float_as_uint(v.y);
}

// ============================================================================
// Linear: C[M,512] = A[M,512] @ W[512,512]^T + bias (+res). tf32 MMA.
// CTA 256(M) x 128(N), K-chunks 64. 8 warps (4m x 2n), warp 64x64.
// ============================================================================
template <bool ADD_RES>
__global__ __launch_bounds__(256, 1) void linear_kernel(
    const float* __restrict__ A, const float* __restrict__ W,
    const float* __restrict__ bias, const float* __restrict__ res,
    float* __restrict__ C)
{
    extern __shared__ float sm[];
    float* AsF = sm;                    // 16*8*ABLK = 16896 floats
    float* WsF = sm + 16 * 8 * ABLK;    // 16*8*BBLK = 8704 floats
    float* stage = sm;                  // epilogue overlay [128][SPL] = 16896 floats

    const int t    = threadIdx.x;
    const int lane = t & 31;
    const int warp = t >> 5;
    const int wm   = warp >> 1;       // 0..3 (64 rows each)
    const int wn   = warp & 1;        // 0..1 (64 cols each)
    const int lr   = lane >> 2;
    const int lc   = lane & 3;
    const int row0 = blockIdx.y * 256;
    const int col0 = blockIdx.x * 128;

    float acc[4][8][4] = {};

    for (int k0 = 0; k0 < DD; k0 += 64) {
        __syncthreads();
#pragma unroll
        for (int i = 0; i < 16; i++) {
            int s = t + 256 * i, r = s >> 4, c4 = (s & 15) * 4;
            float4 v = *(const float4*)&A[(size_t)(row0 + r) * DD + k0 + c4];
            v.x = f2tff(v.x); v.y = f2tff(v.y); v.z = f2tff(v.z); v.w = f2tff(v.w);
            stA4(AsF, r, c4, v);
        }
#pragma unroll
        for (int i = 0; i < 8; i++) {
            int s = t + 256 * i, r = s >> 4, c4 = (s & 15) * 4;
            float4 v = *(const float4*)&W[(size_t)(col0 + r) * DD + k0 + c4];
            v.x = f2tff(v.x); v.y = f2tff(v.y); v.z = f2tff(v.z); v.w = f2tff(v.w);
            stB4(WsF, r, c4, v);
        }
        __syncthreads();

#pragma unroll
        for (int kc = 0; kc < 8; kc++) {
            uint32_t a[4][4], b[8][2];
#pragma unroll
            for (int mi = 0; mi < 4; mi++) ldAfrag(a[mi], AsF, wm * 4 + mi, kc, lane);
#pragma unroll
            for (int ni = 0; ni < 8; ni++) ldBfrag(b[ni], WsF, wn * 8 + ni, kc, lane);
#pragma unroll
            for (int mi = 0; mi < 4; mi++)
#pragma unroll
                for (int ni = 0; ni < 8; ni++)
                    mma_tf32(acc[mi][ni], a[mi], b[ni]);
        }
    }

    // bias
#pragma unroll
    for (int ni = 0; ni < 8; ni++) {
        int c = col0 + wn * 64 + ni * 8 + lc * 2;
        float b0 = bias[c], b1 = bias[c + 1];
#pragma unroll
        for (int mi = 0; mi < 4; mi++) {
            acc[mi][ni][0] += b0; acc[mi][ni][1] += b1;
            acc[mi][ni][2] += b0; acc[mi][ni][3] += b1;
        }
    }

    // two 128-row halves: stage + coalesced store  (stride SPL=132 for 128 cols)
#pragma unroll
    for (int h = 0; h < 2; h++) {
        __syncthreads();
        if ((wm >> 1) == h) {
#pragma unroll
            for (int mi = 0; mi < 4; mi++)
#pragma unroll
                for (int ni = 0; ni < 8; ni++) {
                    int r = (wm & 1) * 64 + mi * 16 + lr;
                    int c = wn * 64 + ni * 8 + lc * 2;
                    stage[r * SPL + c]           = acc[mi][ni][0];
                    stage[r * SPL + c + 1]       = acc[mi][ni][1];
                    stage[(r + 8) * SPL + c]     = acc[mi][ni][2];
                    stage[(r + 8) * SPL + c + 1] = acc[mi][ni][3];
                }
        }
        __syncthreads();
#pragma unroll
        for (int i = 0; i < 16; i++) {
            int s = t + 256 * i, r = s >> 5, c4 = (s & 31) * 4;
            float4 v = *(float4*)&stage[r * SPL + c4];
            size_t g = (size_t)(row0 + h * 128 + r) * DD + col0 + c4;
            if (ADD_RES) {
                float4 rr = *(const float4*)&res[g];
                v.x += rr.x; v.y += rr.y; v.z += rr.z; v.w += rr.w;
            }
            *(float4*)&C[g] = v;
        }
    }
}

// ============================================================================
// Flash pass 0: rowsums of exp(Q@K^T * scale).
// CTA 128 q x kv-tiles of 128. 8 warps (2m x 4n), warp 64x32.
// ============================================================================
__global__ __launch_bounds__(256, 1) void flash0_kernel(
    const float* __restrict__ qlin, const float* __restrict__ klin,
    float* __restrict__ rowsum_out)
{
    extern __shared__ float sm[];
    float* QsF = sm;                    // 8*8*ABLK = 8448
    float* KsF = sm + 8 * 8 * ABLK;     // 16*8*BBLK = 8704
    float* red = KsF + 16 * 8 * BBLK;   // 128*4

    const int bh = blockIdx.y;
    const int b  = bh >> 3;
    const int h  = bh & 7;
    const int q0 = blockIdx.x * 128;

    const int t    = threadIdx.x;
    const int lane = t & 31;
    const int warp = t >> 5;
    const int wm   = warp >> 2;       // 0..1 (64 rows)
    const int wn   = warp & 3;        // 0..3 (32 cols)
    const int lr   = lane >> 2;
    const int lc   = lane & 3;

    const float* Qb = qlin + (size_t)b * SQ * DD + h * HDIM;
    const float* Kb = klin + (size_t)b * SK * DD + h * HDIM;

#pragma unroll
    for (int i = 0; i < 8; i++) {
        int s = t + 256 * i, r = s >> 4, c4 = (s & 15) * 4;
        float4 v = *(const float4*)&Qb[(size_t)(q0 + r) * DD + c4];
        v.x = f2tff(v.x); v.y = f2tff(v.y); v.z = f2tff(v.z); v.w = f2tff(v.w);
        stA4(QsF, r, c4, v);
    }

    float rs[4][2] = {};

    for (int kv0 = 0; kv0 < SK; kv0 += 128) {
        __syncthreads();
#pragma unroll
        for (int i = 0; i < 8; i++) {
            int s = t + 256 * i, r = s >> 4, c4 = (s & 15) * 4;
            float4 v = *(const float4*)&Kb[(size_t)(kv0 + r) * DD + c4];
            v.x = f2tff(v.x); v.y = f2tff(v.y); v.z = f2tff(v.z); v.w = f2tff(v.w);
            stB4(KsF, r, c4, v);
        }
        __syncthreads();

        float acc[4][4][4] = {};
#pragma unroll
        for (int kc = 0; kc < 8; kc++) {
            uint32_t a[4][4], bfr[4][2];
#pragma unroll
            for (int mi = 0; mi < 4; mi++) ldAfrag(a[mi], QsF, wm * 4 + mi, kc, lane);
#pragma unroll
            for (int ni = 0; ni < 4; ni++) ldBfrag(bfr[ni], KsF, wn * 4 + ni, kc, lane);
#pragma unroll
            for (int mi = 0; mi < 4; mi++)
#pragma unroll
                for (int ni = 0; ni < 4; ni++)
                    mma_tf32(acc[mi][ni], a[mi], bfr[ni]);
        }

#pragma unroll
        for (int mi = 0; mi < 4; mi++)
#pragma unroll
            for (int ni = 0; ni < 4; ni++) {
                rs[mi][0] += __expf(acc[mi][ni][0] * FSCALE) + __expf(acc[mi][ni][1] * FSCALE);
                rs[mi][1] += __expf(acc[mi][ni][2] * FSCALE) + __expf(acc[mi][ni][3] * FSCALE);
            }
    }

    // reduce over lc (4 lanes) then over the 4 n-warps
#pragma unroll
    for (int mi = 0; mi < 4; mi++)
#pragma unroll
        for (int hi = 0; hi < 2; hi++) {
            float v = rs[mi][hi];
            v += __shfl_xor_sync(0xFFFFFFFFu, v, 1);
            v += __shfl_xor_sync(0xFFFFFFFFu, v, 2);
            rs[mi][hi] = v;
        }
    if (lc == 0) {
#pragma unroll
        for (int mi = 0; mi < 4; mi++)
#pragma unroll
            for (int hi = 0; hi < 2; hi++)
                red[(wm * 64 + mi * 16 + hi * 8 + lr) * 4 + wn] = rs[mi][hi];
    }
    __syncthreads();
    if (t < 128)
        rowsum_out[(size_t)bh * SQ + q0 + t] =
            (red[t * 4 + 0] + red[t * 4 + 1]) + (red[t * 4 + 2] + red[t * 4 + 3]);
}

// ============================================================================
// Flash pass 1: recompute S, P = exp*inv, write normalized attn, O += P@V.
// CTA 128 q x kv-tiles of 64. 8 warps (4m x 2n), warp 32x32.
// ============================================================================
__global__ __launch_bounds__(256, 1) void flash1_kernel(
    const float* __restrict__ qlin, const float* __restrict__ klin,
    const float* __restrict__ vlin, const float* __restrict__ rowsum_in,
    float* __restrict__ attn, float* __restrict__ ctx)
{
    extern __shared__ float sm[];
    float* QsF = sm;                          // 8448
    float* KsF = QsF + 8 * 8 * ABLK;          // 8*8*BBLK = 4352
    float* VsF = KsF + 8 * 8 * BBLK;          // 4352
    float* Ps  = VsF + 8 * 8 * BBLK;          // 128*SP = 8704
    float* inv = Ps + 128 * SP;               // 128

    const int bh = blockIdx.y;
    const int b  = bh >> 3;
    const int h  = bh & 7;
    const int q0 = blockIdx.x * 128;

    const int t    = threadIdx.x;
    const int lane = t & 31;
    const int warp = t >> 5;
    const int wm   = warp >> 1;   // 0..3
    const int wn   = warp & 1;    // 0..1
    const int lr   = lane >> 2;
    const int lc   = lane & 3;

    const float* Qb = qlin + (size_t)b * SQ * DD + h * HDIM;
    const float* Kb = klin + (size_t)b * SK * DD + h * HDIM;
    const float* Vb = vlin + (size_t)b * SK * DD + h * HDIM;

#pragma unroll
    for (int i = 0; i < 8; i++) {
        int s = t + 256 * i, r = s >> 4, c4 = (s & 15) * 4;
        float4 v = *(const float4*)&Qb[(size_t)(q0 + r) * DD + c4];
        v.x = f2tff(v.x); v.y = f2tff(v.y); v.z = f2tff(v.z); v.w = f2tff(v.w);
        stA4(QsF, r, c4, v);
    }
    if (t < 128)
        inv[t] = 1.0f / rowsum_in[(size_t)bh * SQ + q0 + t];

    float oacc[2][4][4] = {};

    for (int kv0 = 0; kv0 < SK; kv0 += 64) {
        __syncthreads();
#pragma unroll
        for (int i = 0; i < 4; i++) {
            int s = t + 256 * i, r = s >> 4, c4 = (s & 15) * 4;
            float4 v = *(const float4*)&Kb[(size_t)(kv0 + r) * DD + c4];
            v.x = f2tff(v.x); v.y = f2tff(v.y); v.z = f2tff(v.z); v.w = f2tff(v.w);
            stB4(KsF, r, c4, v);
            float4 w = *(const float4*)&Vb[(size_t)(kv0 + r) * DD + c4];
            w.x = f2tff(w.x); w.y = f2tff(w.y); w.z = f2tff(w.z); w.w = f2tff(w.w);
            stV4(VsF, r, c4, w);
        }
        __syncthreads();

        // GEMM1: S(128x64) = Q @ K^T
        float acc[2][4][4] = {};
#pragma unroll
        for (int kc = 0; kc < 8; kc++) {
            uint32_t a[2][4], bfr[4][2];
#pragma unroll
            for (int mi = 0; mi < 2; mi++) ldAfrag(a[mi], QsF, wm * 2 + mi, kc, lane);
#pragma unroll
            for (int ni = 0; ni < 4; ni++) ldBfrag(bfr[ni], KsF, wn * 4 + ni, kc, lane);
#pragma unroll
            for (int mi = 0; mi < 2; mi++)
#pragma unroll
                for (int ni = 0; ni < 4; ni++)
                    mma_tf32(acc[mi][ni], a[mi], bfr[ni]);
        }

        // exp + normalize into Ps (full fp32 for the attn output)
#pragma unroll
        for (int mi = 0; mi < 2; mi++) {
            int r = wm * 32 + mi * 16 + lr;
            float iv0 = inv[r], iv1 = inv[r + 8];
#pragma unroll
            for (int ni = 0; ni < 4; ni++) {
                int c = wn * 32 + ni * 8 + lc * 2;
                Ps[r * SP + c]           = __expf(acc[mi][ni][0] * FSCALE) * iv0;
                Ps[r * SP + c + 1]       = __expf(acc[mi][ni][1] * FSCALE) * iv0;
                Ps[(r + 8) * SP + c]     = __expf(acc[mi][ni][2] * FSCALE) * iv1;
                Ps[(r + 8) * SP + c + 1] = __expf(acc[mi][ni][3] * FSCALE) * iv1;
            }
        }
        __syncthreads();

        // coalesced attn write
        float* arow = attn + ((size_t)bh * SQ + q0) * SK + kv0;
#pragma unroll
        for (int i = 0; i < 8; i++) {
            int s = t + 256 * i, r = s >> 4, c4 = (s & 15) * 4;
            *(float4*)&arow[(size_t)r * SK + c4] = *(float4*)&Ps[r * SP + c4];
        }

        // GEMM2: O += P(128x64) @ V(64x64)
#pragma unroll
        for (int kc = 0; kc < 8; kc++) {
            uint32_t a[2][4], bfr[4][2];
#pragma unroll
            for (int mi = 0; mi < 2; mi++) {
                const float* p = &Ps[(wm * 32 + mi * 16 + lr) * SP + kc * 8 + lc];
                a[mi][0] = f2tf(p[0]);
                a[mi][1] = f2tf(p[8 * SP]);
                a[mi][2] = f2tf(p[4]);
                a[mi][3] = f2tf(p[8 * SP + 4]);
            }
#pragma unroll
            for (int ni = 0; ni < 4; ni++) ldBfrag(bfr[ni], VsF, wn * 4 + ni, kc, lane);
#pragma unroll
            for (int mi = 0; mi < 2; mi++)
#pragma unroll
                for (int ni = 0; ni < 4; ni++)
                    mma_tf32(oacc[mi][ni], a[mi], bfr[ni]);
        }
    }

    // O epilogue via Ps
    __syncthreads();
#pragma unroll
    for (int mi = 0; mi < 2; mi++)
#pragma unroll
        for (int ni = 0; ni < 4; ni++) {
            int r = wm * 32 + mi * 16 + lr;
            int c = wn * 32 + ni * 8 + lc * 2;
            Ps[r * SP + c]           = oacc[mi][ni][0];
            Ps[r * SP + c + 1]       = oacc[mi][ni][1];
            Ps[(r + 8) * SP + c]     = oacc[mi][ni][2];
            Ps[(r + 8) * SP + c + 1] = oacc[mi][ni][3];
        }
    __syncthreads();
#pragma unroll
    for (int i = 0; i < 8; i++) {
        int s = t + 256 * i, r = s >> 4, c4 = (s & 15) * 4;
        *(float4*)&ctx[(size_t)(b * SQ + q0 + r) * DD + h * HDIM + c4] =
            *(float4*)&Ps[r * SP + c4];
    }
}

// ============================================================================
// LayerNorm in-place
// ============================================================================
__global__ __launch_bounds__(128) void ln_kernel(
    float* __restrict__ out, const float* __restrict__ g,
    const float* __restrict__ bta)
{
    __shared__ float red[128];
    const size_t row = blockIdx.x;
    float* p = out + row * (size_t)DD;
    const int t = threadIdx.x;

    float4 v = ((const float4*)p)[t];
    red[t] = v.x + v.y + v.z + v.w;
    __syncthreads();
    for (int s = 64; s > 0; s >>= 1) {
        if (t < s) red[t] += red[t + s];
        __syncthreads();
    }
    float mu = red[0] * (1.0f / DD);
    __syncthreads();

    float dx = v.x - mu, dy = v.y - mu, dz = v.z - mu, dw = v.w - mu;
    red[t] = dx * dx + dy * dy + dz * dz + dw * dw;
    __syncthreads();
    for (int s = 64; s > 0; s >>= 1) {
        if (t < s) red[t] += red[t + s];
        __syncthreads();
    }
    float rstd = rsqrtf(red[0] * (1.0f / DD) + LNEPS);

    float4 gg = ((const float4*)g)[t];
    float4 bb = ((const float4*)bta)[t];
    float4 o;
    o.x = dx * rstd * gg.x + bb.x;
    o.y = dy * rstd * gg.y + bb.y;
    o.z = dz * rstd * gg.z + bb.z;
    o.w = dw * rstd * gg.w + bb.w;
    ((float4*)p)[t] = o;
}

// ============================================================================
// Launch
// ============================================================================
#define SMEM_LIN ((16 * 8 * ABLK + 16 * 8 * BBLK) * 4)                         /* 102400 */
#define SMEM_FL0 ((8 * 8 * ABLK + 16 * 8 * BBLK + 512) * 4)                    /* 70656  */
#define SMEM_FL1 ((8 * 8 * ABLK + 2 * 8 * 8 * BBLK + 128 * SP + 128) * 4)      /* 103936 */

extern "C" void kernel_launch(void* const* d_in, const int* in_sizes, int n_in,
                              void* d_out, int out_size)
{
    const float* q   = (const float*)d_in[0];
    const float* k   = (const float*)d_in[1];
    const float* v   = (const float*)d_in[2];
    const float* Wq  = (const float*)d_in[3];
    const float* bq  = (const float*)d_in[4];
    const float* Wk  = (const float*)d_in[5];
    const float* bk  = (const float*)d_in[6];
    const float* Wv  = (const float*)d_in[7];
    const float* bv  = (const float*)d_in[8];
    const float* Wo  = (const float*)d_in[9];
    const float* bo  = (const float*)d_in[10];
    const float* lng = (const float*)d_in[11];
    const float* lnb = (const float*)d_in[12];

    float* out = (float*)d_out;

    float *qlin, *klin, *vlin, *ctx, *attn_scr, *rowsum;
    cudaGetSymbolAddress((void**)&qlin, g_qlin);
    cudaGetSymbolAddress((void**)&klin, g_klin);
    cudaGetSymbolAddress((void**)&vlin, g_vlin);
    cudaGetSymbolAddress((void**)&ctx,  g_ctx);
    cudaGetSymbolAddress((void**)&attn_scr, g_attn_scratch);
    cudaGetSymbolAddress((void**)&rowsum, g_rowsum);

    float* attn = ((size_t)out_size >= OUT_ELEMS + ATTN_ELEMS)
                      ? out + OUT_ELEMS : attn_scr;

    cudaFuncSetAttribute(linear_kernel<false>,
                         cudaFuncAttributeMaxDynamicSharedMemorySize, SMEM_LIN);
    cudaFuncSetAttribute(linear_kernel<true>,
                         cudaFuncAttributeMaxDynamicSharedMemorySize, SMEM_LIN);
    cudaFuncSetAttribute(flash0_kernel,
                         cudaFuncAttributeMaxDynamicSharedMemorySize, SMEM_FL0);
    cudaFuncSetAttribute(flash1_kernel,
                         cudaFuncAttributeMaxDynamicSharedMemorySize, SMEM_FL1);

    dim3 blk(256);

    // 1) projections (CTA 256x128 -> 128 CTAs, single wave)
    dim3 gLin(DD / 128, (BB * SQ) / 256);
    linear_kernel<false><<<gLin, blk, SMEM_LIN>>>(q, Wq, bq, nullptr, qlin);
    linear_kernel<false><<<gLin, blk, SMEM_LIN>>>(k, Wk, bk, nullptr, klin);
    linear_kernel<false><<<gLin, blk, SMEM_LIN>>>(v, Wv, bv, nullptr, vlin);

    // 2) pass A: row sums of exp(S)
    dim3 gFl(SQ / 128, BB * HH);
    flash0_kernel<<<gFl, blk, SMEM_FL0>>>(qlin, klin, rowsum);

    // 3) pass B: normalized attn write + O = P@V
    flash1_kernel<<<gFl, blk, SMEM_FL1>>>(qlin, klin, vlin, rowsum, attn, ctx);

    // 4) output projection + residual(q_lin)
    linear_kernel<true><<<gLin, blk, SMEM_LIN>>>(ctx, Wo, bo, qlin, out);

    // 5) layernorm
    ln_kernel<<<BB * SQ, dim3(128)>>>(out, lng, lnb);
}

// round 8
// speedup vs baseline: 1.9083x; 1.9083x over previous
#include <cuda_runtime.h>
#include <cuda_fp16.h>
#include <math.h>
#include <stdint.h>

#define BB 4
#define SQ 2048
#define SK 2048
#define DD 512
#define HH 8
#define HDIM 64
#define FSCALE 0.125f
#define LNEPS 1e-5f

#define OUT_ELEMS ((size_t)BB * SQ * DD)
#define ATTN_ELEMS ((size_t)BB * HH * SQ * (size_t)SK)

#define PS 72     /* smem half-tile row stride (halves): 144B rows -> LDSM conflict-free */
#define SP 68     /* fp32 staging stride (floats) */

// ---- scratch ----
__device__ float  g_qlin[BB * SQ * DD];
__device__ float  g_klin[BB * SK * DD];
__device__ float  g_vlin[BB * SK * DD];
__device__ float  g_ctx [BB * SQ * DD];
__device__ __half g_qh[BB * SQ * DD];
__device__ __half g_kh[BB * SK * DD];
__device__ __half g_vh[BB * SK * DD];
__device__ float  g_rowsum[(size_t)BB * HH * SQ];
__device__ float  g_attn_scratch[ATTN_ELEMS];

// ---- mma / ldmatrix helpers ----
__device__ __forceinline__ uint32_t sptr(const void* p) {
    return (uint32_t)__cvta_generic_to_shared(p);
}

__device__ __forceinline__ void mma_f16(float* c, const uint32_t* a, const uint32_t* b) {
    asm volatile(
        "mma.sync.aligned.m16n8k16.row.col.f32.f16.f16.f32 "
        "{%0,%1,%2,%3}, {%4,%5,%6,%7}, {%8,%9}, {%0,%1,%2,%3};"
        : "+f"(c[0]), "+f"(c[1]), "+f"(c[2]), "+f"(c[3])
        : "r"(a[0]), "r"(a[1]), "r"(a[2]), "r"(a[3]), "r"(b[0]), "r"(b[1]));
}

// A-fragment: 16x16 tile at (row0, k0) of row-major [row][k] half tile.
__device__ __forceinline__ void ldmA(uint32_t* a, const __half* base, int row0, int k0, int lane) {
    const __half* p = base + (size_t)(row0 + (lane & 7) + ((lane >> 3) & 1) * 8) * PS
                      + k0 + (lane >> 4) * 8;
    asm volatile("ldmatrix.sync.aligned.m8n8.x4.shared.b16 {%0,%1,%2,%3}, [%4];"
                 : "=r"(a[0]), "=r"(a[1]), "=r"(a[2]), "=r"(a[3]) : "r"(sptr(p)));
}
// B-fragments for TWO 8-wide n-tiles (n0..n0+15) from row-major [n][k] half tile.
// regs b[0..1] -> n-tile at n0, b[2..3] -> n-tile at n0+8.
__device__ __forceinline__ void ldmB2(uint32_t* b, const __half* base, int n0, int k0, int lane) {
    const __half* p = base + (size_t)(n0 + (lane & 7) + (lane >> 4) * 8) * PS
                      + k0 + ((lane >> 3) & 1) * 8;
    asm volatile("ldmatrix.sync.aligned.m8n8.x4.shared.b16 {%0,%1,%2,%3}, [%4];"
                 : "=r"(b[0]), "=r"(b[1]), "=r"(b[2]), "=r"(b[3]) : "r"(sptr(p)));
}
// B-fragments for TWO n-tiles from row-major [k][n] half tile (transpose load, for V).
__device__ __forceinline__ void ldmBt2(uint32_t* b, const __half* base, int k0, int n0, int lane) {
    const __half* p = base + (size_t)(k0 + (lane & 7) + ((lane >> 3) & 1) * 8) * PS
                      + n0 + (lane >> 4) * 8;
    asm volatile("ldmatrix.sync.aligned.m8n8.x4.trans.shared.b16 {%0,%1,%2,%3}, [%4];"
                 : "=r"(b[0]), "=r"(b[1]), "=r"(b[2]), "=r"(b[3]) : "r"(sptr(p)));
}

// ============================================================================
// Linear: C[M,512] = A[M,512] @ W[512,512]^T + bias (+res), optional half copy.
// CTA 128(M) x 64(N), k-chunks 64. 8 warps (4m x 2n), warp 32x32. fp16 MMA.
// ============================================================================
template <bool ADD_RES, bool WRITE_H>
__global__ __launch_bounds__(256, 2) void linear_kernel(
    const float* __restrict__ A, const float* __restrict__ W,
    const float* __restrict__ bias, const float* __restrict__ res,
    float* __restrict__ C, __half* __restrict__ Ch)
{
    extern __shared__ char smc[];
    __half* Ah = (__half*)smc;                 // [128][PS] = 18432 B
    __half* Wh = (__half*)(smc + 128 * PS * 2);// [64][PS]  = 9216 B
    float* stage = (float*)smc;                // overlay [128][SP] = 34816 B

    const int t    = threadIdx.x;
    const int lane = t & 31;
    const int warp = t >> 5;
    const int wm   = warp >> 1;
    const int wn   = warp & 1;
    const int lr   = lane >> 2;
    const int lc   = lane & 3;
    const int row0 = blockIdx.y * 128;
    const int col0 = blockIdx.x * 64;

    float acc[2][4][4] = {};

    for (int k0 = 0; k0 < DD; k0 += 64) {
        __syncthreads();
#pragma unroll
        for (int i = 0; i < 8; i++) {
            int s = t + 256 * i, r = s >> 4, c4 = (s & 15) * 4;
            float4 v = *(const float4*)&A[(size_t)(row0 + r) * DD + k0 + c4];
            *(half2*)&Ah[r * PS + c4]     = __floats2half2_rn(v.x, v.y);
            *(half2*)&Ah[r * PS + c4 + 2] = __floats2half2_rn(v.z, v.w);
        }
#pragma unroll
        for (int i = 0; i < 4; i++) {
            int s = t + 256 * i, r = s >> 4, c4 = (s & 15) * 4;
            float4 v = *(const float4*)&W[(size_t)(col0 + r) * DD + k0 + c4];
            *(half2*)&Wh[r * PS + c4]     = __floats2half2_rn(v.x, v.y);
            *(half2*)&Wh[r * PS + c4 + 2] = __floats2half2_rn(v.z, v.w);
        }
        __syncthreads();

#pragma unroll
        for (int kc = 0; kc < 4; kc++) {
            uint32_t a[2][4], bfr[2][4];
            ldmA(a[0], Ah, wm * 32,      kc * 16, lane);
            ldmA(a[1], Ah, wm * 32 + 16, kc * 16, lane);
            ldmB2(bfr[0], Wh, wn * 32,      kc * 16, lane);
            ldmB2(bfr[1], Wh, wn * 32 + 16, kc * 16, lane);
#pragma unroll
            for (int mi = 0; mi < 2; mi++)
#pragma unroll
                for (int ni = 0; ni < 4; ni++)
                    mma_f16(acc[mi][ni], a[mi], &bfr[ni >> 1][(ni & 1) * 2]);
        }
    }

    // bias
#pragma unroll
    for (int ni = 0; ni < 4; ni++) {
        int c = col0 + wn * 32 + ni * 8 + lc * 2;
        float b0 = bias[c], b1 = bias[c + 1];
#pragma unroll
        for (int mi = 0; mi < 2; mi++) {
            acc[mi][ni][0] += b0; acc[mi][ni][1] += b1;
            acc[mi][ni][2] += b0; acc[mi][ni][3] += b1;
        }
    }

    // stage + coalesced store
    __syncthreads();
#pragma unroll
    for (int mi = 0; mi < 2; mi++)
#pragma unroll
        for (int ni = 0; ni < 4; ni++) {
            int r = wm * 32 + mi * 16 + lr;
            int c = wn * 32 + ni * 8 + lc * 2;
            stage[r * SP + c]           = acc[mi][ni][0];
            stage[r * SP + c + 1]       = acc[mi][ni][1];
            stage[(r + 8) * SP + c]     = acc[mi][ni][2];
            stage[(r + 8) * SP + c + 1] = acc[mi][ni][3];
        }
    __syncthreads();
#pragma unroll
    for (int i = 0; i < 8; i++) {
        int s = t + 256 * i, r = s >> 4, c4 = (s & 15) * 4;
        float4 v = *(float4*)&stage[r * SP + c4];
        size_t g = (size_t)(row0 + r) * DD + col0 + c4;
        if (ADD_RES) {
            float4 rr = *(const float4*)&res[g];
            v.x += rr.x; v.y += rr.y; v.z += rr.z; v.w += rr.w;
        }
        *(float4*)&C[g] = v;
        if (WRITE_H) {
            half2 h0 = __floats2half2_rn(v.x, v.y);
            half2 h1 = __floats2half2_rn(v.z, v.w);
            *(half2*)&Ch[g]     = h0;
            *(half2*)&Ch[g + 2] = h1;
        }
    }
}

// ============================================================================
// Flash pass 0: rowsums of exp(Q@K^T * scale). fp16 MMA.
// CTA 128 q x kv-tiles 64. 8 warps (4m x 2n), warp 32x32.
// ============================================================================
__global__ __launch_bounds__(256, 2) void flash0_kernel(
    const __half* __restrict__ qh, const __half* __restrict__ kh,
    float* __restrict__ rowsum_out)
{
    extern __shared__ char smc[];
    __half* Qh = (__half*)smc;                  // [128][PS] = 18432
    __half* Kh = (__half*)(smc + 128 * PS * 2); // [64][PS]  = 9216
    float*  red = (float*)(smc + 128 * PS * 2 + 64 * PS * 2); // [128][2]

    const int bh = blockIdx.y;
    const int b  = bh >> 3;
    const int h  = bh & 7;
    const int q0 = blockIdx.x * 128;

    const int t    = threadIdx.x;
    const int lane = t & 31;
    const int warp = t >> 5;
    const int wm   = warp >> 1;
    const int wn   = warp & 1;
    const int lr   = lane >> 2;
    const int lc   = lane & 3;

    const __half* Qb = qh + (size_t)b * SQ * DD + h * HDIM;
    const __half* Kb = kh + (size_t)b * SK * DD + h * HDIM;

#pragma unroll
    for (int i = 0; i < 8; i++) {
        int s = t + 256 * i, r = s >> 4, c4 = (s & 15) * 4;
        *(uint2*)&Qh[r * PS + c4] = *(const uint2*)&Qb[(size_t)(q0 + r) * DD + c4];
    }

    float rs[2][2] = {};

    for (int kv0 = 0; kv0 < SK; kv0 += 64) {
        __syncthreads();
#pragma unroll
        for (int i = 0; i < 4; i++) {
            int s = t + 256 * i, r = s >> 4, c4 = (s & 15) * 4;
            *(uint2*)&Kh[r * PS + c4] = *(const uint2*)&Kb[(size_t)(kv0 + r) * DD + c4];
        }
        __syncthreads();

        float acc[2][4][4] = {};
#pragma unroll
        for (int kc = 0; kc < 4; kc++) {
            uint32_t a[2][4], bfr[2][4];
            ldmA(a[0], Qh, wm * 32,      kc * 16, lane);
            ldmA(a[1], Qh, wm * 32 + 16, kc * 16, lane);
            ldmB2(bfr[0], Kh, wn * 32,      kc * 16, lane);
            ldmB2(bfr[1], Kh, wn * 32 + 16, kc * 16, lane);
#pragma unroll
            for (int mi = 0; mi < 2; mi++)
#pragma unroll
                for (int ni = 0; ni < 4; ni++)
                    mma_f16(acc[mi][ni], a[mi], &bfr[ni >> 1][(ni & 1) * 2]);
        }

#pragma unroll
        for (int mi = 0; mi < 2; mi++)
#pragma unroll
            for (int ni = 0; ni < 4; ni++) {
                rs[mi][0] += __expf(acc[mi][ni][0] * FSCALE) + __expf(acc[mi][ni][1] * FSCALE);
                rs[mi][1] += __expf(acc[mi][ni][2] * FSCALE) + __expf(acc[mi][ni][3] * FSCALE);
            }
    }

#pragma unroll
    for (int mi = 0; mi < 2; mi++)
#pragma unroll
        for (int hf = 0; hf < 2; hf++) {
            float v = rs[mi][hf];
            v += __shfl_xor_sync(0xFFFFFFFFu, v, 1);
            v += __shfl_xor_sync(0xFFFFFFFFu, v, 2);
            rs[mi][hf] = v;
        }
    if (lc == 0) {
#pragma unroll
        for (int mi = 0; mi < 2; mi++)
#pragma unroll
            for (int hf = 0; hf < 2; hf++)
                red[(wm * 32 + mi * 16 + hf * 8 + lr) * 2 + wn] = rs[mi][hf];
    }
    __syncthreads();
    if (t < 128)
        rowsum_out[(size_t)bh * SQ + q0 + t] = red[t * 2 + 0] + red[t * 2 + 1];
}

// ============================================================================
// Flash pass 1: recompute S, P = exp*inv; write normalized attn (fp32, direct);
// O += P@V via fp16 MMA (P exchanged through smem as half).
// CTA 128 q x kv-tiles 64. 8 warps (4m x 2n), warp 32x32.
// ============================================================================
__global__ __launch_bounds__(256, 2) void flash1_kernel(
    const __half* __restrict__ qh, const __half* __restrict__ kh,
    const __half* __restrict__ vh, const float* __restrict__ rowsum_in,
    float* __restrict__ attn, float* __restrict__ ctx)
{
    extern __shared__ char smc[];
    __half* Qh  = (__half*)smc;                              // 18432
    __half* Kh  = (__half*)(smc + 18432);                    // 9216
    __half* Vh  = (__half*)(smc + 18432 + 9216);             // 9216 ([kv][d])
    __half* Psh = (__half*)(smc + 18432 + 9216 + 9216);      // [128][PS] = 18432
    float*  inv = (float*)(smc + 18432 + 9216 + 9216 + 18432); // 512

    const int bh = blockIdx.y;
    const int b  = bh >> 3;
    const int h  = bh & 7;
    const int q0 = blockIdx.x * 128;

    const int t    = threadIdx.x;
    const int lane = t & 31;
    const int warp = t >> 5;
    const int wm   = warp >> 1;
    const int wn   = warp & 1;
    const int lr   = lane >> 2;
    const int lc   = lane & 3;

    const __half* Qb = qh + (size_t)b * SQ * DD + h * HDIM;
    const __half* Kb = kh + (size_t)b * SK * DD + h * HDIM;
    const __half* Vb = vh + (size_t)b * SK * DD + h * HDIM;

#pragma unroll
    for (int i = 0; i < 8; i++) {
        int s = t + 256 * i, r = s >> 4, c4 = (s & 15) * 4;
        *(uint2*)&Qh[r * PS + c4] = *(const uint2*)&Qb[(size_t)(q0 + r) * DD + c4];
    }
    if (t < 128)
        inv[t] = 1.0f / rowsum_in[(size_t)bh * SQ + q0 + t];

    float oacc[2][4][4] = {};
    float* arow = attn + ((size_t)bh * SQ + q0) * SK;

    for (int kv0 = 0; kv0 < SK; kv0 += 64) {
        __syncthreads();
#pragma unroll
        for (int i = 0; i < 4; i++) {
            int s = t + 256 * i, r = s >> 4, c4 = (s & 15) * 4;
            *(uint2*)&Kh[r * PS + c4] = *(const uint2*)&Kb[(size_t)(kv0 + r) * DD + c4];
            *(uint2*)&Vh[r * PS + c4] = *(const uint2*)&Vb[(size_t)(kv0 + r) * DD + c4];
        }
        __syncthreads();

        // GEMM1: S(128x64) = Q @ K^T
        float acc[2][4][4] = {};
#pragma unroll
        for (int kc = 0; kc < 4; kc++) {
            uint32_t a[2][4], bfr[2][4];
            ldmA(a[0], Qh, wm * 32,      kc * 16, lane);
            ldmA(a[1], Qh, wm * 32 + 16, kc * 16, lane);
            ldmB2(bfr[0], Kh, wn * 32,      kc * 16, lane);
            ldmB2(bfr[1], Kh, wn * 32 + 16, kc * 16, lane);
#pragma unroll
            for (int mi = 0; mi < 2; mi++)
#pragma unroll
                for (int ni = 0; ni < 4; ni++)
                    mma_f16(acc[mi][ni], a[mi], &bfr[ni >> 1][(ni & 1) * 2]);
        }

        // exp * inv: write attn (fp32, direct) + Psh (half, for GEMM2)
#pragma unroll
        for (int mi = 0; mi < 2; mi++) {
            int r = wm * 32 + mi * 16 + lr;
            float iv0 = inv[r], iv1 = inv[r + 8];
#pragma unroll
            for (int ni = 0; ni < 4; ni++) {
                int c = wn * 32 + ni * 8 + lc * 2;
                float e0 = __expf(acc[mi][ni][0] * FSCALE) * iv0;
                float e1 = __expf(acc[mi][ni][1] * FSCALE) * iv0;
                float e2 = __expf(acc[mi][ni][2] * FSCALE) * iv1;
                float e3 = __expf(acc[mi][ni][3] * FSCALE) * iv1;
                *(float2*)&arow[(size_t)r * SK + kv0 + c]       = make_float2(e0, e1);
                *(float2*)&arow[(size_t)(r + 8) * SK + kv0 + c] = make_float2(e2, e3);
                *(half2*)&Psh[r * PS + c]       = __floats2half2_rn(e0, e1);
                *(half2*)&Psh[(r + 8) * PS + c] = __floats2half2_rn(e2, e3);
            }
        }
        __syncthreads();

        // GEMM2: O += P(128x64) @ V(64x64)
#pragma unroll
        for (int kc = 0; kc < 4; kc++) {
            uint32_t a[2][4], bfr[2][4];
            ldmA(a[0], Psh, wm * 32,      kc * 16, lane);
            ldmA(a[1], Psh, wm * 32 + 16, kc * 16, lane);
            ldmBt2(bfr[0], Vh, kc * 16, wn * 32,      lane);
            ldmBt2(bfr[1], Vh, kc * 16, wn * 32 + 16, lane);
#pragma unroll
            for (int mi = 0; mi < 2; mi++)
#pragma unroll
                for (int ni = 0; ni < 4; ni++)
                    mma_f16(oacc[mi][ni], a[mi], &bfr[ni >> 1][(ni & 1) * 2]);
        }
    }

    // O epilogue: direct float2 stores
#pragma unroll
    for (int mi = 0; mi < 2; mi++) {
        size_t r0 = (size_t)b * SQ + q0 + wm * 32 + mi * 16 + lr;
#pragma unroll
        for (int ni = 0; ni < 4; ni++) {
            int c = h * HDIM + wn * 32 + ni * 8 + lc * 2;
            *(float2*)&ctx[r0 * DD + c]       = make_float2(oacc[mi][ni][0], oacc[mi][ni][1]);
            *(float2*)&ctx[(r0 + 8) * DD + c] = make_float2(oacc[mi][ni][2], oacc[mi][ni][3]);
        }
    }
}

// ============================================================================
// LayerNorm in-place
// ============================================================================
__global__ __launch_bounds__(128) void ln_kernel(
    float* __restrict__ out, const float* __restrict__ g,
    const float* __restrict__ bta)
{
    __shared__ float red[128];
    const size_t row = blockIdx.x;
    float* p = out + row * (size_t)DD;
    const int t = threadIdx.x;

    float4 v = ((const float4*)p)[t];
    red[t] = v.x + v.y + v.z + v.w;
    __syncthreads();
    for (int s = 64; s > 0; s >>= 1) {
        if (t < s) red[t] += red[t + s];
        __syncthreads();
    }
    float mu = red[0] * (1.0f / DD);
    __syncthreads();

    float dx = v.x - mu, dy = v.y - mu, dz = v.z - mu, dw = v.w - mu;
    red[t] = dx * dx + dy * dy + dz * dz + dw * dw;
    __syncthreads();
    for (int s = 64; s > 0; s >>= 1) {
        if (t < s) red[t] += red[t + s];
        __syncthreads();
    }
    float rstd = rsqrtf(red[0] * (1.0f / DD) + LNEPS);

    float4 gg = ((const float4*)g)[t];
    float4 bb = ((const float4*)bta)[t];
    float4 o;
    o.x = dx * rstd * gg.x + bb.x;
    o.y = dy * rstd * gg.y + bb.y;
    o.z = dz * rstd * gg.z + bb.z;
    o.w = dw * rstd * gg.w + bb.w;
    ((float4*)p)[t] = o;
}

// ============================================================================
// Launch
// ============================================================================
#define SMEM_LIN 34816                                   /* fp32 stage overlay dominates */
#define SMEM_F0  (18432 + 9216 + 1024)                   /* 28672 */
#define SMEM_F1  (18432 + 9216 + 9216 + 18432 + 512)     /* 55808 */

extern "C" void kernel_launch(void* const* d_in, const int* in_sizes, int n_in,
                              void* d_out, int out_size)
{
    const float* q   = (const float*)d_in[0];
    const float* k   = (const float*)d_in[1];
    const float* v   = (const float*)d_in[2];
    const float* Wq  = (const float*)d_in[3];
    const float* bq  = (const float*)d_in[4];
    const float* Wk  = (const float*)d_in[5];
    const float* bk  = (const float*)d_in[6];
    const float* Wv  = (const float*)d_in[7];
    const float* bv  = (const float*)d_in[8];
    const float* Wo  = (const float*)d_in[9];
    const float* bo  = (const float*)d_in[10];
    const float* lng = (const float*)d_in[11];
    const float* lnb = (const float*)d_in[12];

    float* out = (float*)d_out;

    float *qlin, *klin, *vlin, *ctx, *attn_scr, *rowsum;
    __half *qh, *kh, *vh;
    cudaGetSymbolAddress((void**)&qlin, g_qlin);
    cudaGetSymbolAddress((void**)&klin, g_klin);
    cudaGetSymbolAddress((void**)&vlin, g_vlin);
    cudaGetSymbolAddress((void**)&ctx,  g_ctx);
    cudaGetSymbolAddress((void**)&attn_scr, g_attn_scratch);
    cudaGetSymbolAddress((void**)&rowsum, g_rowsum);
    cudaGetSymbolAddress((void**)&qh, g_qh);
    cudaGetSymbolAddress((void**)&kh, g_kh);
    cudaGetSymbolAddress((void**)&vh, g_vh);

    float* attn = ((size_t)out_size >= OUT_ELEMS + ATTN_ELEMS)
                      ? out + OUT_ELEMS : attn_scr;

    cudaFuncSetAttribute((const void*)linear_kernel<false, true>,
                         cudaFuncAttributeMaxDynamicSharedMemorySize, SMEM_LIN);
    cudaFuncSetAttribute((const void*)linear_kernel<true, false>,
                         cudaFuncAttributeMaxDynamicSharedMemorySize, SMEM_LIN);
    cudaFuncSetAttribute((const void*)flash0_kernel,
                         cudaFuncAttributeMaxDynamicSharedMemorySize, SMEM_F0);
    cudaFuncSetAttribute((const void*)flash1_kernel,
                         cudaFuncAttributeMaxDynamicSharedMemorySize, SMEM_F1);

    dim3 blk(256);

    // 1) projections (fp32 + fp16 outputs)
    dim3 gLin(DD / 64, (BB * SQ) / 128);
    linear_kernel<false, true><<<gLin, blk, SMEM_LIN>>>(q, Wq, bq, nullptr, qlin, qh);
    linear_kernel<false, true><<<gLin, blk, SMEM_LIN>>>(k, Wk, bk, nullptr, klin, kh);
    linear_kernel<false, true><<<gLin, blk, SMEM_LIN>>>(v, Wv, bv, nullptr, vlin, vh);

    // 2) pass A: row sums of exp(S)
    dim3 gFl(SQ / 128, BB * HH);
    flash0_kernel<<<gFl, blk, SMEM_F0>>>(qh, kh, rowsum);

    // 3) pass B: normalized attn write + O = P@V
    flash1_kernel<<<gFl, blk, SMEM_F1>>>(qh, kh, vh, rowsum, attn, ctx);

    // 4) output projection + residual(q_lin)
    linear_kernel<true, false><<<gLin, blk, SMEM_LIN>>>(ctx, Wo, bo, qlin, out, nullptr);

    // 5) layernorm
    ln_kernel<<<BB * SQ, dim3(128)>>>(out, lng, lnb);
}

// round 9
// speedup vs baseline: 2.3126x; 1.2119x over previous
#include <cuda_runtime.h>
#include <cuda_fp16.h>
#include <math.h>
#include <stdint.h>

#define BB 4
#define SQ 2048
#define SK 2048
#define DD 512
#define HH 8
#define HDIM 64
#define FSCALE 0.125f
#define LOG2E 1.44269504088896f
#define LNEPS 1e-5f

#define OUT_ELEMS ((size_t)BB * SQ * DD)
#define ATTN_ELEMS ((size_t)BB * HH * SQ * (size_t)SK)

#define PS 72     /* smem half-tile row stride (halves): 144B rows */
#define SP 68     /* fp32 staging stride (floats) */

// ---- scratch ----
__device__ float  g_qlin[BB * SQ * DD];
__device__ float  g_ctx_unused[1];
__device__ __half g_qh[BB * SQ * DD];
__device__ __half g_kh[BB * SK * DD];
__device__ __half g_vh[BB * SK * DD];
__device__ __half g_ctxh[BB * SQ * DD];
__device__ __half g_inqh[BB * SQ * DD];
__device__ __half g_inkh[BB * SK * DD];
__device__ __half g_invh[BB * SK * DD];
__device__ __half g_Wqh[DD * DD];
__device__ __half g_Wkh[DD * DD];
__device__ __half g_Wvh[DD * DD];
__device__ __half g_Woh[DD * DD];
__device__ float  g_rowsum[(size_t)BB * HH * SQ];
__device__ float  g_attn_scratch[ATTN_ELEMS];

// ---- helpers ----
__device__ __forceinline__ uint32_t sptr(const void* p) {
    return (uint32_t)__cvta_generic_to_shared(p);
}
__device__ __forceinline__ void cp16(uint32_t dst, const void* src) {
    asm volatile("cp.async.ca.shared.global [%0], [%1], 16;" :: "r"(dst), "l"(src));
}
#define CP_COMMIT() asm volatile("cp.async.commit_group;")
#define CP_WAIT1()  asm volatile("cp.async.wait_group 1;")
#define CP_WAIT0()  asm volatile("cp.async.wait_group 0;")

__device__ __forceinline__ float fexp2(float x) {
    float y;
    asm("ex2.approx.f32 %0, %1;" : "=f"(y) : "f"(x));
    return y;
}

__device__ __forceinline__ void mma_f16(float* c, const uint32_t* a, const uint32_t* b) {
    asm volatile(
        "mma.sync.aligned.m16n8k16.row.col.f32.f16.f16.f32 "
        "{%0,%1,%2,%3}, {%4,%5,%6,%7}, {%8,%9}, {%0,%1,%2,%3};"
        : "+f"(c[0]), "+f"(c[1]), "+f"(c[2]), "+f"(c[3])
        : "r"(a[0]), "r"(a[1]), "r"(a[2]), "r"(a[3]), "r"(b[0]), "r"(b[1]));
}

__device__ __forceinline__ void ldmA(uint32_t* a, const __half* base, int row0, int k0, int lane) {
    const __half* p = base + (size_t)(row0 + (lane & 7) + ((lane >> 3) & 1) * 8) * PS
                      + k0 + (lane >> 4) * 8;
    asm volatile("ldmatrix.sync.aligned.m8n8.x4.shared.b16 {%0,%1,%2,%3}, [%4];"
                 : "=r"(a[0]), "=r"(a[1]), "=r"(a[2]), "=r"(a[3]) : "r"(sptr(p)));
}
__device__ __forceinline__ void ldmB2(uint32_t* b, const __half* base, int n0, int k0, int lane) {
    const __half* p = base + (size_t)(n0 + (lane & 7) + (lane >> 4) * 8) * PS
                      + k0 + ((lane >> 3) & 1) * 8;
    asm volatile("ldmatrix.sync.aligned.m8n8.x4.shared.b16 {%0,%1,%2,%3}, [%4];"
                 : "=r"(b[0]), "=r"(b[1]), "=r"(b[2]), "=r"(b[3]) : "r"(sptr(p)));
}
__device__ __forceinline__ void ldmBt2(uint32_t* b, const __half* base, int k0, int n0, int lane) {
    const __half* p = base + (size_t)(k0 + (lane & 7) + ((lane >> 3) & 1) * 8) * PS
                      + n0 + (lane >> 4) * 8;
    asm volatile("ldmatrix.sync.aligned.m8n8.x4.trans.shared.b16 {%0,%1,%2,%3}, [%4];"
                 : "=r"(b[0]), "=r"(b[1]), "=r"(b[2]), "=r"(b[3]) : "r"(sptr(p)));
}

// ============================================================================
// fp32 -> fp16 conversion (grid-stride over float4)
// ============================================================================
__global__ __launch_bounds__(256) void to_half_kernel(
    const float* __restrict__ src, __half* __restrict__ dst, int n4)
{
    int i = blockIdx.x * 256 + threadIdx.x;
    if (i < n4) {
        float4 v = ((const float4*)src)[i];
        ((half2*)dst)[i * 2]     = __floats2half2_rn(v.x, v.y);
        ((half2*)dst)[i * 2 + 1] = __floats2half2_rn(v.z, v.w);
    }
}

// ============================================================================
// Linear (half inputs): C[M,512] = A@W^T + bias (+res fp32).
// Outputs fp32 C and/or half Ch (Ch scaled by hscale).
// CTA 128x64, k-chunks 64 double-buffered via cp.async. 8 warps, warp 32x32.
// ============================================================================
template <bool ADD_RES, bool WRITE_F, bool WRITE_H>
__global__ __launch_bounds__(256, 2) void linear_kernel(
    const __half* __restrict__ A, const __half* __restrict__ W,
    const float* __restrict__ bias, const float* __restrict__ res,
    float* __restrict__ C, __half* __restrict__ Ch, float hscale)
{
    extern __shared__ char smc[];
    __half* Ah = (__half*)smc;                       // 2 x [128][PS] = 36864 B
    __half* Wh = (__half*)(smc + 2 * 128 * PS * 2);  // 2 x [64][PS]  = 18432 B
    float* stage = (float*)smc;                      // overlay 34816 B

    const int t    = threadIdx.x;
    const int lane = t & 31;
    const int warp = t >> 5;
    const int wm   = warp >> 1;
    const int wn   = warp & 1;
    const int lr   = lane >> 2;
    const int lc   = lane & 3;
    const int row0 = blockIdx.y * 128;
    const int col0 = blockIdx.x * 64;

    const uint32_t ah0 = sptr(Ah);
    const uint32_t wh0 = sptr(Wh);

    // issue chunk 0
    {
#pragma unroll
        for (int i = 0; i < 4; i++) {
            int s = t + 256 * i, r = s >> 3, c8 = (s & 7) * 8;
            cp16(ah0 + (r * PS + c8) * 2, &A[(size_t)(row0 + r) * DD + c8]);
        }
#pragma unroll
        for (int i = 0; i < 2; i++) {
            int s = t + 256 * i, r = s >> 3, c8 = (s & 7) * 8;
            cp16(wh0 + (r * PS + c8) * 2, &W[(size_t)(col0 + r) * DD + c8]);
        }
        CP_COMMIT();
    }

    float acc[2][4][4] = {};

    for (int kc0 = 0; kc0 < 8; kc0++) {
        __syncthreads();   // safe buffer reuse
        if (kc0 + 1 < 8) {
            int k0 = (kc0 + 1) * 64;
            int nb = (kc0 + 1) & 1;
#pragma unroll
            for (int i = 0; i < 4; i++) {
                int s = t + 256 * i, r = s >> 3, c8 = (s & 7) * 8;
                cp16(ah0 + (nb * 128 * PS + r * PS + c8) * 2,
                     &A[(size_t)(row0 + r) * DD + k0 + c8]);
            }
#pragma unroll
            for (int i = 0; i < 2; i++) {
                int s = t + 256 * i, r = s >> 3, c8 = (s & 7) * 8;
                cp16(wh0 + (nb * 64 * PS + r * PS + c8) * 2,
                     &W[(size_t)(col0 + r) * DD + k0 + c8]);
            }
            CP_COMMIT();
            CP_WAIT1();
        } else {
            CP_WAIT0();
        }
        __syncthreads();

        const __half* Ab = Ah + (kc0 & 1) * 128 * PS;
        const __half* Wb = Wh + (kc0 & 1) * 64 * PS;
#pragma unroll
        for (int kc = 0; kc < 4; kc++) {
            uint32_t a[2][4], bfr[2][4];
            ldmA(a[0], Ab, wm * 32,      kc * 16, lane);
            ldmA(a[1], Ab, wm * 32 + 16, kc * 16, lane);
            ldmB2(bfr[0], Wb, wn * 32,      kc * 16, lane);
            ldmB2(bfr[1], Wb, wn * 32 + 16, kc * 16, lane);
#pragma unroll
            for (int mi = 0; mi < 2; mi++)
#pragma unroll
                for (int ni = 0; ni < 4; ni++)
                    mma_f16(acc[mi][ni], a[mi], &bfr[ni >> 1][(ni & 1) * 2]);
        }
    }

    // bias
#pragma unroll
    for (int ni = 0; ni < 4; ni++) {
        int c = col0 + wn * 32 + ni * 8 + lc * 2;
        float b0 = bias[c], b1 = bias[c + 1];
#pragma unroll
        for (int mi = 0; mi < 2; mi++) {
            acc[mi][ni][0] += b0; acc[mi][ni][1] += b1;
            acc[mi][ni][2] += b0; acc[mi][ni][3] += b1;
        }
    }

    // stage + coalesced store
    __syncthreads();
#pragma unroll
    for (int mi = 0; mi < 2; mi++)
#pragma unroll
        for (int ni = 0; ni < 4; ni++) {
            int r = wm * 32 + mi * 16 + lr;
            int c = wn * 32 + ni * 8 + lc * 2;
            stage[r * SP + c]           = acc[mi][ni][0];
            stage[r * SP + c + 1]       = acc[mi][ni][1];
            stage[(r + 8) * SP + c]     = acc[mi][ni][2];
            stage[(r + 8) * SP + c + 1] = acc[mi][ni][3];
        }
    __syncthreads();
#pragma unroll
    for (int i = 0; i < 8; i++) {
        int s = t + 256 * i, r = s >> 4, c4 = (s & 15) * 4;
        float4 v = *(float4*)&stage[r * SP + c4];
        size_t g = (size_t)(row0 + r) * DD + col0 + c4;
        if (ADD_RES) {
            float4 rr = *(const float4*)&res[g];
            v.x += rr.x; v.y += rr.y; v.z += rr.z; v.w += rr.w;
        }
        if (WRITE_F) *(float4*)&C[g] = v;
        if (WRITE_H) {
            *(half2*)&Ch[g]     = __floats2half2_rn(v.x * hscale, v.y * hscale);
            *(half2*)&Ch[g + 2] = __floats2half2_rn(v.z * hscale, v.w * hscale);
        }
    }
}

// ============================================================================
// Flash pass 0: rowsums of exp2(Qs@K^T) (Q pre-scaled by FSCALE*LOG2E).
// CTA 128 q x kv 64, K double-buffered cp.async. 8 warps (4m x 2n).
// ============================================================================
__global__ __launch_bounds__(256, 2) void flash0_kernel(
    const __half* __restrict__ qh, const __half* __restrict__ kh,
    float* __restrict__ rowsum_out)
{
    extern __shared__ char smc[];
    __half* Qh = (__half*)smc;                      // [128][PS] = 18432
    __half* Kh = (__half*)(smc + 128 * PS * 2);     // 2 x [64][PS] = 18432
    float*  red = (float*)(smc + 128 * PS * 2 + 2 * 64 * PS * 2); // [128][2]

    const int bh = blockIdx.y;
    const int b  = bh >> 3;
    const int h  = bh & 7;
    const int q0 = blockIdx.x * 128;

    const int t    = threadIdx.x;
    const int lane = t & 31;
    const int warp = t >> 5;
    const int wm   = warp >> 1;
    const int wn   = warp & 1;
    const int lr   = lane >> 2;
    const int lc   = lane & 3;

    const __half* Qb = qh + (size_t)b * SQ * DD + h * HDIM;
    const __half* Kb = kh + (size_t)b * SK * DD + h * HDIM;
    const uint32_t kh0 = sptr(Kh);

    // Q tile (once)
#pragma unroll
    for (int i = 0; i < 8; i++) {
        int s = t + 256 * i, r = s >> 4, c4 = (s & 15) * 4;
        *(uint2*)&Qh[r * PS + c4] = *(const uint2*)&Qb[(size_t)(q0 + r) * DD + c4];
    }

    // issue K tile 0
#pragma unroll
    for (int i = 0; i < 2; i++) {
        int s = t + 256 * i, r = s >> 3, c8 = (s & 7) * 8;
        cp16(kh0 + (r * PS + c8) * 2, &Kb[(size_t)r * DD + c8]);
    }
    CP_COMMIT();

    float rs[2][2] = {};

    for (int it = 0; it < SK / 64; it++) {
        __syncthreads();
        if (it + 1 < SK / 64) {
            int kv = (it + 1) * 64;
            int nb = (it + 1) & 1;
#pragma unroll
            for (int i = 0; i < 2; i++) {
                int s = t + 256 * i, r = s >> 3, c8 = (s & 7) * 8;
                cp16(kh0 + (nb * 64 * PS + r * PS + c8) * 2,
                     &Kb[(size_t)(kv + r) * DD + c8]);
            }
            CP_COMMIT();
            CP_WAIT1();
        } else {
            CP_WAIT0();
        }
        __syncthreads();

        const __half* Kb_s = Kh + (it & 1) * 64 * PS;
        float acc[2][4][4] = {};
#pragma unroll
        for (int kc = 0; kc < 4; kc++) {
            uint32_t a[2][4], bfr[2][4];
            ldmA(a[0], Qh, wm * 32,      kc * 16, lane);
            ldmA(a[1], Qh, wm * 32 + 16, kc * 16, lane);
            ldmB2(bfr[0], Kb_s, wn * 32,      kc * 16, lane);
            ldmB2(bfr[1], Kb_s, wn * 32 + 16, kc * 16, lane);
#pragma unroll
            for (int mi = 0; mi < 2; mi++)
#pragma unroll
                for (int ni = 0; ni < 4; ni++)
                    mma_f16(acc[mi][ni], a[mi], &bfr[ni >> 1][(ni & 1) * 2]);
        }

#pragma unroll
        for (int mi = 0; mi < 2; mi++)
#pragma unroll
            for (int ni = 0; ni < 4; ni++) {
                rs[mi][0] += fexp2(acc[mi][ni][0]) + fexp2(acc[mi][ni][1]);
                rs[mi][1] += fexp2(acc[mi][ni][2]) + fexp2(acc[mi][ni][3]);
            }
    }

#pragma unroll
    for (int mi = 0; mi < 2; mi++)
#pragma unroll
        for (int hf = 0; hf < 2; hf++) {
            float v = rs[mi][hf];
            v += __shfl_xor_sync(0xFFFFFFFFu, v, 1);
            v += __shfl_xor_sync(0xFFFFFFFFu, v, 2);
            rs[mi][hf] = v;
        }
    if (lc == 0) {
#pragma unroll
        for (int mi = 0; mi < 2; mi++)
#pragma unroll
            for (int hf = 0; hf < 2; hf++)
                red[(wm * 32 + mi * 16 + hf * 8 + lr) * 2 + wn] = rs[mi][hf];
    }
    __syncthreads();
    if (t < 128)
        rowsum_out[(size_t)bh * SQ + q0 + t] = red[t * 2 + 0] + red[t * 2 + 1];
}

// ============================================================================
// Flash pass 1: recompute S, P = exp2*inv; write attn fp32; O += P@V -> ctx_h.
// K,V double-buffered cp.async. CTA 128 q x kv 64. 8 warps (4m x 2n).
// ============================================================================
__global__ __launch_bounds__(256, 2) void flash1_kernel(
    const __half* __restrict__ qh, const __half* __restrict__ kh,
    const __half* __restrict__ vh, const float* __restrict__ rowsum_in,
    float* __restrict__ attn, __half* __restrict__ ctxh)
{
    extern __shared__ char smc[];
    __half* Qh  = (__half*)smc;                        // 18432
    __half* Kh  = (__half*)(smc + 18432);              // 2 x 9216
    __half* Vh  = (__half*)(smc + 18432 + 18432);      // 2 x 9216
    __half* Psh = (__half*)(smc + 18432 + 36864);      // 18432
    float*  inv = (float*)(smc + 18432 + 36864 + 18432); // 512

    const int bh = blockIdx.y;
    const int b  = bh >> 3;
    const int h  = bh & 7;
    const int q0 = blockIdx.x * 128;

    const int t    = threadIdx.x;
    const int lane = t & 31;
    const int warp = t >> 5;
    const int wm   = warp >> 1;
    const int wn   = warp & 1;
    const int lr   = lane >> 2;
    const int lc   = lane & 3;

    const __half* Qb = qh + (size_t)b * SQ * DD + h * HDIM;
    const __half* Kb = kh + (size_t)b * SK * DD + h * HDIM;
    const __half* Vb = vh + (size_t)b * SK * DD + h * HDIM;
    const uint32_t kh0 = sptr(Kh);
    const uint32_t vh0 = sptr(Vh);

#pragma unroll
    for (int i = 0; i < 8; i++) {
        int s = t + 256 * i, r = s >> 4, c4 = (s & 15) * 4;
        *(uint2*)&Qh[r * PS + c4] = *(const uint2*)&Qb[(size_t)(q0 + r) * DD + c4];
    }
    if (t < 128)
        inv[t] = 1.0f / rowsum_in[(size_t)bh * SQ + q0 + t];

    // issue K,V tile 0
#pragma unroll
    for (int i = 0; i < 2; i++) {
        int s = t + 256 * i, r = s >> 3, c8 = (s & 7) * 8;
        cp16(kh0 + (r * PS + c8) * 2, &Kb[(size_t)r * DD + c8]);
        cp16(vh0 + (r * PS + c8) * 2, &Vb[(size_t)r * DD + c8]);
    }
    CP_COMMIT();

    float oacc[2][4][4] = {};
    float* arow = attn + ((size_t)bh * SQ + q0) * SK;

    for (int it = 0; it < SK / 64; it++) {
        int kv0 = it * 64;
        __syncthreads();
        if (it + 1 < SK / 64) {
            int kv = kv0 + 64;
            int nb = (it + 1) & 1;
#pragma unroll
            for (int i = 0; i < 2; i++) {
                int s = t + 256 * i, r = s >> 3, c8 = (s & 7) * 8;
                cp16(kh0 + (nb * 64 * PS + r * PS + c8) * 2, &Kb[(size_t)(kv + r) * DD + c8]);
                cp16(vh0 + (nb * 64 * PS + r * PS + c8) * 2, &Vb[(size_t)(kv + r) * DD + c8]);
            }
            CP_COMMIT();
            CP_WAIT1();
        } else {
            CP_WAIT0();
        }
        __syncthreads();

        const __half* Kb_s = Kh + (it & 1) * 64 * PS;
        const __half* Vb_s = Vh + (it & 1) * 64 * PS;

        // GEMM1: S(128x64) = Q @ K^T
        float acc[2][4][4] = {};
#pragma unroll
        for (int kc = 0; kc < 4; kc++) {
            uint32_t a[2][4], bfr[2][4];
            ldmA(a[0], Qh, wm * 32,      kc * 16, lane);
            ldmA(a[1], Qh, wm * 32 + 16, kc * 16, lane);
            ldmB2(bfr[0], Kb_s, wn * 32,      kc * 16, lane);
            ldmB2(bfr[1], Kb_s, wn * 32 + 16, kc * 16, lane);
#pragma unroll
            for (int mi = 0; mi < 2; mi++)
#pragma unroll
                for (int ni = 0; ni < 4; ni++)
                    mma_f16(acc[mi][ni], a[mi], &bfr[ni >> 1][(ni & 1) * 2]);
        }

        // exp2 * inv: attn (fp32 direct) + Psh (half)
#pragma unroll
        for (int mi = 0; mi < 2; mi++) {
            int r = wm * 32 + mi * 16 + lr;
            float iv0 = inv[r], iv1 = inv[r + 8];
#pragma unroll
            for (int ni = 0; ni < 4; ni++) {
                int c = wn * 32 + ni * 8 + lc * 2;
                float e0 = fexp2(acc[mi][ni][0]) * iv0;
                float e1 = fexp2(acc[mi][ni][1]) * iv0;
                float e2 = fexp2(acc[mi][ni][2]) * iv1;
                float e3 = fexp2(acc[mi][ni][3]) * iv1;
                *(float2*)&arow[(size_t)r * SK + kv0 + c]       = make_float2(e0, e1);
                *(float2*)&arow[(size_t)(r + 8) * SK + kv0 + c] = make_float2(e2, e3);
                *(half2*)&Psh[r * PS + c]       = __floats2half2_rn(e0, e1);
                *(half2*)&Psh[(r + 8) * PS + c] = __floats2half2_rn(e2, e3);
            }
        }
        __syncthreads();

        // GEMM2: O += P(128x64) @ V(64x64)
#pragma unroll
        for (int kc = 0; kc < 4; kc++) {
            uint32_t a[2][4], bfr[2][4];
            ldmA(a[0], Psh, wm * 32,      kc * 16, lane);
            ldmA(a[1], Psh, wm * 32 + 16, kc * 16, lane);
            ldmBt2(bfr[0], Vb_s, kc * 16, wn * 32,      lane);
            ldmBt2(bfr[1], Vb_s, kc * 16, wn * 32 + 16, lane);
#pragma unroll
            for (int mi = 0; mi < 2; mi++)
#pragma unroll
                for (int ni = 0; ni < 4; ni++)
                    mma_f16(oacc[mi][ni], a[mi], &bfr[ni >> 1][(ni & 1) * 2]);
        }
    }

    // O epilogue: half2 stores to ctxh
#pragma unroll
    for (int mi = 0; mi < 2; mi++) {
        size_t r0 = (size_t)b * SQ + q0 + wm * 32 + mi * 16 + lr;
#pragma unroll
        for (int ni = 0; ni < 4; ni++) {
            int c = h * HDIM + wn * 32 + ni * 8 + lc * 2;
            *(half2*)&ctxh[r0 * DD + c]       = __floats2half2_rn(oacc[mi][ni][0], oacc[mi][ni][1]);
            *(half2*)&ctxh[(r0 + 8) * DD + c] = __floats2half2_rn(oacc[mi][ni][2], oacc[mi][ni][3]);
        }
    }
}

// ============================================================================
// LayerNorm in-place
// ============================================================================
__global__ __launch_bounds__(128) void ln_kernel(
    float* __restrict__ out, const float* __restrict__ g,
    const float* __restrict__ bta)
{
    __shared__ float red[128];
    const size_t row = blockIdx.x;
    float* p = out + row * (size_t)DD;
    const int t = threadIdx.x;

    float4 v = ((const float4*)p)[t];
    red[t] = v.x + v.y + v.z + v.w;
    __syncthreads();
    for (int s = 64; s > 0; s >>= 1) {
        if (t < s) red[t] += red[t + s];
        __syncthreads();
    }
    float mu = red[0] * (1.0f / DD);
    __syncthreads();

    float dx = v.x - mu, dy = v.y - mu, dz = v.z - mu, dw = v.w - mu;
    red[t] = dx * dx + dy * dy + dz * dz + dw * dw;
    __syncthreads();
    for (int s = 64; s > 0; s >>= 1) {
        if (t < s) red[t] += red[t + s];
        __syncthreads();
    }
    float rstd = rsqrtf(red[0] * (1.0f / DD) + LNEPS);

    float4 gg = ((const float4*)g)[t];
    float4 bb = ((const float4*)bta)[t];
    float4 o;
    o.x = dx * rstd * gg.x + bb.x;
    o.y = dy * rstd * gg.y + bb.y;
    o.z = dz * rstd * gg.z + bb.z;
    o.w = dw * rstd * gg.w + bb.w;
    ((float4*)p)[t] = o;
}

// ============================================================================
// Launch
// ============================================================================
#define SMEM_LIN (2 * 128 * PS * 2 + 2 * 64 * PS * 2)            /* 55296 */
#define SMEM_F0  (128 * PS * 2 + 2 * 64 * PS * 2 + 1024)          /* 37888 */
#define SMEM_F1  (18432 + 18432 + 18432 + 18432 + 512)            /* 74240 */

extern "C" void kernel_launch(void* const* d_in, const int* in_sizes, int n_in,
                              void* d_out, int out_size)
{
    const float* q   = (const float*)d_in[0];
    const float* k   = (const float*)d_in[1];
    const float* v   = (const float*)d_in[2];
    const float* Wq  = (const float*)d_in[3];
    const float* bq  = (const float*)d_in[4];
    const float* Wk  = (const float*)d_in[5];
    const float* bk  = (const float*)d_in[6];
    const float* Wv  = (const float*)d_in[7];
    const float* bv  = (const float*)d_in[8];
    const float* Wo  = (const float*)d_in[9];
    const float* bo  = (const float*)d_in[10];
    const float* lng = (const float*)d_in[11];
    const float* lnb = (const float*)d_in[12];

    float* out = (float*)d_out;

    float *qlin, *attn_scr, *rowsum;
    __half *qh, *kh, *vh, *ctxh, *inqh, *inkh, *invh, *Wqh, *Wkh, *Wvh, *Woh;
    cudaGetSymbolAddress((void**)&qlin, g_qlin);
    cudaGetSymbolAddress((void**)&attn_scr, g_attn_scratch);
    cudaGetSymbolAddress((void**)&rowsum, g_rowsum);
    cudaGetSymbolAddress((void**)&qh, g_qh);
    cudaGetSymbolAddress((void**)&kh, g_kh);
    cudaGetSymbolAddress((void**)&vh, g_vh);
    cudaGetSymbolAddress((void**)&ctxh, g_ctxh);
    cudaGetSymbolAddress((void**)&inqh, g_inqh);
    cudaGetSymbolAddress((void**)&inkh, g_inkh);
    cudaGetSymbolAddress((void**)&invh, g_invh);
    cudaGetSymbolAddress((void**)&Wqh, g_Wqh);
    cudaGetSymbolAddress((void**)&Wkh, g_Wkh);
    cudaGetSymbolAddress((void**)&Wvh, g_Wvh);
    cudaGetSymbolAddress((void**)&Woh, g_Woh);

    float* attn = ((size_t)out_size >= OUT_ELEMS + ATTN_ELEMS)
                      ? out + OUT_ELEMS : attn_scr;

    cudaFuncSetAttribute((const void*)linear_kernel<false, true, true>,
                         cudaFuncAttributeMaxDynamicSharedMemorySize, SMEM_LIN);
    cudaFuncSetAttribute((const void*)linear_kernel<false, false, true>,
                         cudaFuncAttributeMaxDynamicSharedMemorySize, SMEM_LIN);
    cudaFuncSetAttribute((const void*)linear_kernel<true, true, false>,
                         cudaFuncAttributeMaxDynamicSharedMemorySize, SMEM_LIN);
    cudaFuncSetAttribute((const void*)flash0_kernel,
                         cudaFuncAttributeMaxDynamicSharedMemorySize, SMEM_F0);
    cudaFuncSetAttribute((const void*)flash1_kernel,
                         cudaFuncAttributeMaxDynamicSharedMemorySize, SMEM_F1);

    dim3 blk(256);

    // 0) fp16 conversions
    const int NIN4 = (BB * SQ * DD) / 4;    // 1,048,576
    const int NW4  = (DD * DD) / 4;         // 65,536
    to_half_kernel<<<(NIN4 + 255) / 256, blk>>>(q, inqh, NIN4);
    to_half_kernel<<<(NIN4 + 255) / 256, blk>>>(k, inkh, NIN4);
    to_half_kernel<<<(NIN4 + 255) / 256, blk>>>(v, invh, NIN4);
    to_half_kernel<<<(NW4 + 255) / 256, blk>>>(Wq, Wqh, NW4);
    to_half_kernel<<<(NW4 + 255) / 256, blk>>>(Wk, Wkh, NW4);
    to_half_kernel<<<(NW4 + 255) / 256, blk>>>(Wv, Wvh, NW4);
    to_half_kernel<<<(NW4 + 255) / 256, blk>>>(Wo, Woh, NW4);

    // 1) projections. qh is pre-scaled by FSCALE*LOG2E for exp2-based softmax.
    dim3 gLin(DD / 64, (BB * SQ) / 128);
    linear_kernel<false, true, true><<<gLin, blk, SMEM_LIN>>>(
        inqh, Wqh, bq, nullptr, qlin, qh, FSCALE * LOG2E);
    linear_kernel<false, false, true><<<gLin, blk, SMEM_LIN>>>(
        inkh, Wkh, bk, nullptr, nullptr, kh, 1.0f);
    linear_kernel<false, false, true><<<gLin, blk, SMEM_LIN>>>(
        invh, Wvh, bv, nullptr, nullptr, vh, 1.0f);

    // 2) pass A: row sums
    dim3 gFl(SQ / 128, BB * HH);
    flash0_kernel<<<gFl, blk, SMEM_F0>>>(qh, kh, rowsum);

    // 3) pass B: normalized attn + O = P@V (half ctx)
    flash1_kernel<<<gFl, blk, SMEM_F1>>>(qh, kh, vh, rowsum, attn, ctxh);

    // 4) output projection + residual(q_lin)
    linear_kernel<true, true, false><<<gLin, blk, SMEM_LIN>>>(
        ctxh, Woh, bo, qlin, out, nullptr, 1.0f);

    // 5) layernorm
    ln_kernel<<<BB * SQ, dim3(128)>>>(out, lng, lnb);
}